// round 11
// baseline (speedup 1.0000x reference)
#include <cuda_runtime.h>

#define EPSF 1e-8f
#define LNK   16
#define DST   255
#define TUN   1020
#define NCH   8
#define PAIRS 28          // row pairs per block
#define ROWS  56
#define SSTR  58          // words per group slot (28 pairs*2 + 2 pad)
#define PLW   (32*SSTR)   // 1856 words per plane
#define BUFDW (4*PLW)     // 7424 data words per buffer
#define BUFW  (BUFDW+64)  // + 64-word zero region per buffer
#define BUFB  (BUFW*4)    // 29952 bytes per buffer
#define ZBYTE (BUFDW*4)   // 29696: zero region byte offset (same in all buffers)
#define SCHW  144
#define THR   512

// dynamic smem layout (words)
#define W_SCHED (3*BUFW)                  // 22464
#define W_OFF   (W_SCHED + (NCH*SCHW)/2)  // + 576
#define W_CUR   (W_OFF + NCH*17)
#define W_NL    (W_CUR + NCH*17)
#define W_INV   (W_NL + ROWS*17)
#define W_LOSS  (W_INV + 16)
#define W_FIN   (W_LOSS + 16)
#define W_LAST  (W_FIN + THR)
#define W_TOTAL (W_LAST + 1)

__device__ float    g_partials[512];
__device__ unsigned g_count;   // zero-init; last block resets (deterministic)

__device__ __forceinline__ unsigned long long lds64(unsigned a) {
    unsigned long long v;
    asm volatile("ld.shared.b64 %0, [%1];" : "=l"(v) : "r"(a));
    return v;
}
__device__ __forceinline__ unsigned long long addx2(unsigned long long a,
                                                    unsigned long long b) {
    unsigned long long r;
    asm("add.rn.f32x2 %0, %1, %2;" : "=l"(r) : "l"(a), "l"(b));
    return r;
}

__global__ __launch_bounds__(THR, 2) void loss_kernel(
    const float* __restrict__ pred,   // [B,1020]
    const float* __restrict__ dem,    // [B,255]
    const float* __restrict__ clu,    // [B,16]
    const float* __restrict__ caps,   // [16]
    const int*   __restrict__ t2l,    // [1020]
    float* __restrict__ out,
    int B, int nb, float invB)
{
    extern __shared__ float sm[];
    float*          s_pl    = sm;                          // 3 buffers
    unsigned short* s_sched = (unsigned short*)(sm + W_SCHED);
    int*            s_off   = (int*)(sm + W_OFF);          // [8][17]
    int*            s_cur   = (int*)(sm + W_CUR);
    float*          s_nl    = sm + W_NL;                   // [56][17]
    float*          s_inv   = sm + W_INV;
    float*          s_loss  = sm + W_LOSS;
    float*          s_fin   = sm + W_FIN;
    int*            s_last  = (int*)(sm + W_LAST);

    const int tid  = threadIdx.x;
    const int warp = tid >> 5;          // 0..15; stages pairs warp, warp+16; gathers bin=warp
    const int lane = tid & 31;
    const int base = blockIdx.x * ROWS;
    const unsigned pl32 = (unsigned)__cvta_generic_to_shared(s_pl);

    float4 ra[2], rb[2];
    float  da[2], db[2];

    // load pair u of chunk ch into regs
    #define LOADU(ch, u)                                                          \
    {                                                                             \
        const int gg = (ch) * 32 + lane;                                          \
        const int pr = warp + 16 * (u);                                           \
        const int r0 = base + pr, r1 = r0 + PAIRS;                                \
        const bool ok = (pr < PAIRS) && (gg < DST);                               \
        const bool o0 = ok && (r0 < B), o1 = ok && (r1 < B);                      \
        ra[u] = o0 ? ((const float4*)pred)[(size_t)r0 * DST + gg]                 \
                   : make_float4(0,0,0,0);                                        \
        rb[u] = o1 ? ((const float4*)pred)[(size_t)r1 * DST + gg]                 \
                   : make_float4(0,0,0,0);                                        \
        da[u] = o0 ? dem[(size_t)r0 * DST + gg] : 0.0f;                           \
        db[u] = o1 ? dem[(size_t)r1 * DST + gg] : 0.0f;                           \
    }

    // store pair u from regs into buffer buf
    #define STSU(buf, u)                                                          \
    {                                                                             \
        float* bp = s_pl + (buf) * BUFW;                                          \
        const int pr = warp + 16 * (u);                                           \
        if (pr < PAIRS) {                                                         \
            const int wb = lane * SSTR + pr * 2;                                  \
            ((float2*)bp)[(0 * PLW + wb) >> 1] = make_float2(ra[u].x * da[u], rb[u].x * db[u]); \
            ((float2*)bp)[(1 * PLW + wb) >> 1] = make_float2(ra[u].y * da[u], rb[u].y * db[u]); \
            ((float2*)bp)[(2 * PLW + wb) >> 1] = make_float2(ra[u].z * da[u], rb[u].z * db[u]); \
            ((float2*)bp)[(3 * PLW + wb) >> 1] = make_float2(ra[u].w * da[u], rb[u].w * db[u]); \
        }                                                                         \
    }

    // ------------- LDG chunk 0 ----------------------------------------------
    LOADU(0, 0); LOADU(0, 1);

    // ------------- schedule build: warp c (<8) sorts chunk c ----------------
    if (warp < 8) {
        const int c = warp;
        int* cur = s_cur + c * 17;
        int* off = s_off + c * 17;
        if (lane < 17) cur[lane] = 0;
        int bins[4];
        #pragma unroll
        for (int q = 0; q < 4; ++q) {
            const int t = c * 128 + q * 32 + lane;
            bins[q] = (t < TUN) ? t2l[t] : 16;
        }
        __syncwarp();
        #pragma unroll
        for (int q = 0; q < 4; ++q) {
            const unsigned peers = __match_any_sync(0xffffffffu, bins[q]);
            const int rank = __popc(peers & ((1u << lane) - 1u));
            if (rank == 0) cur[bins[q]] += __popc(peers);
            __syncwarp();
        }
        if (lane < 17) {                           // padded (even) exclusive scan
            int o = 0;
            for (int i = 0; i < lane; ++i) o += (cur[i] + 1) & ~1;
            off[lane] = o;
        }
        __syncwarp();
        for (int i = lane; i < SCHW; i += 32)
            s_sched[c * SCHW + i] = (unsigned short)ZBYTE;   // dummy -> zeros
        if (lane < 17) cur[lane] = off[lane];
        __syncwarp();
        #pragma unroll
        for (int q = 0; q < 4; ++q) {
            const unsigned peers = __match_any_sync(0xffffffffu, bins[q]);
            const int rank = __popc(peers & ((1u << lane) - 1u));
            const int bse  = cur[bins[q]];
            __syncwarp();
            if (rank == 0) cur[bins[q]] = bse + __popc(peers);
            __syncwarp();
            if (bins[q] < 16) {
                const int tl = q * 32 + lane;                  // chunk-local id
                const unsigned o = (unsigned)(tl & 3) * (PLW * 4)
                                 + (unsigned)(tl >> 2) * (SSTR * 4);
                s_sched[c * SCHW + bse + rank] = (unsigned short)o;
            }
        }
    }
    // zero regions of all THREE buffers (64 words each)
    if (tid >= 256 && tid < 448) {
        const int i = tid - 256;                   // 0..191
        s_pl[(i >> 6) * BUFW + BUFDW + (i & 63)] = 0.0f;
    }
    if (tid < LNK) s_inv[tid] = 1.0f / (caps[tid] + EPSF);

    // stage chunk 0 -> buffer 0; refill regs with chunk 1
    STSU(0, 0); LOADU(1, 0);
    STSU(0, 1); LOADU(1, 1);
    __syncthreads();

    // ------------- main loop: STS(c+1)|LOAD(c+2) -> gather(c) -> sync -------
    unsigned long long acc0 = 0ull, acc1 = 0ull;

    #pragma unroll 1
    for (int c = 0; c < NCH; ++c) {
        const int bnext = (c + 1) % 3;
        if (c < NCH - 1) {
            if (c < NCH - 2) {
                STSU(bnext, 0); LOADU(c + 2, 0);   // LDGs issue early, land next iter
                STSU(bnext, 1); LOADU(c + 2, 1);
            } else {
                STSU(bnext, 0); STSU(bnext, 1);
            }
        }

        // gather chunk c from buffer c%3; warp owns bin = warp
        {
            const unsigned lbase = pl32 + (unsigned)((c % 3) * BUFB)
                                 + (unsigned)(lane << 3);
            const unsigned short* sc = s_sched + c * SCHW;
            int k = s_off[c * 17 + warp];
            const int hi = s_off[c * 17 + warp + 1];
            #pragma unroll 2
            for (; k < hi; k += 2) {
                const unsigned o0 = sc[k];
                const unsigned o1 = sc[k + 1];
                acc0 = addx2(acc0, lds64(lbase + o0));
                acc1 = addx2(acc1, lds64(lbase + o1));
            }
        }
        __syncthreads();
    }

    // ------------- stats -----------------------------------------------------
    {
        const unsigned long long t = addx2(acc0, acc1);
        const float lo = __uint_as_float((unsigned)(t & 0xffffffffull));
        const float hi = __uint_as_float((unsigned)(t >> 32));
        if (lane < PAIRS) {
            s_nl[lane * 17 + warp] = lo;               // row = lane
            s_nl[(lane + PAIRS) * 17 + warp] = hi;     // row = lane + 28
        }
    }
    __syncthreads();

    float lsum = 0.0f;
    #pragma unroll
    for (int p = 0; p < 2; ++p) {
        const int rid = p * 32 + (warp << 1) + (lane >> 4);
        const int j = lane & 15;
        const int brow = base + rid;
        const bool rok = (rid < ROWS) && (brow < B);
        const float u   = rok ? s_nl[rid * 17 + j] * s_inv[j] : 0.0f;
        const float cur = rok ? clu[(size_t)brow * LNK + j] : 0.0f;

        float smn = u;
        #pragma unroll
        for (int off = 1; off < 16; off <<= 1)
            smn += __shfl_xor_sync(0xffffffffu, smn, off);
        const float mean = smn * (1.0f / 16.0f);

        const float dv = u - mean;
        float q2  = dv * dv;
        float dot = u * cur;
        float mx  = u;
        #pragma unroll
        for (int off = 1; off < 16; off <<= 1) {
            q2  += __shfl_xor_sync(0xffffffffu, q2, off);
            dot += __shfl_xor_sync(0xffffffffu, dot, off);
            mx   = fmaxf(mx, __shfl_xor_sync(0xffffffffu, mx, off));
        }
        if (j == 0 && rok)
            lsum += 0.3f * (q2 * (1.0f / 15.0f)) + 0.5f * dot + 0.2f * mx;
    }
    lsum += __shfl_xor_sync(0xffffffffu, lsum, 16);
    if (lane == 0) s_loss[warp] = lsum;
    __syncthreads();

    // ------------- deterministic single-launch reduction --------------------
    if (tid == 0) {
        float t = 0.0f;
        #pragma unroll
        for (int w = 0; w < 16; ++w) t += s_loss[w];
        g_partials[blockIdx.x] = t;
        __threadfence();
        const unsigned old = atomicAdd(&g_count, 1u);
        *s_last = (old == (unsigned)(nb - 1));
    }
    __syncthreads();

    if (*s_last) {
        float v = 0.0f;
        for (int i = tid; i < nb; i += THR) v += __ldcg(&g_partials[i]);
        s_fin[tid] = v;
        __syncthreads();
        #pragma unroll
        for (int st = 256; st > 0; st >>= 1) {
            if (tid < st) s_fin[tid] += s_fin[tid + st];
            __syncthreads();
        }
        if (tid == 0) {
            out[0] = s_fin[0] * invB;
            g_count = 0;
        }
    }
}

extern "C" void kernel_launch(void* const* d_in, const int* in_sizes, int n_in,
                              void* d_out, int out_size)
{
    const float* pred = (const float*)d_in[0];
    const float* dem  = (const float*)d_in[1];
    const float* clu  = (const float*)d_in[2];
    const float* caps = (const float*)d_in[3];
    const int*   t2l  = (const int*)d_in[4];
    float* out = (float*)d_out;

    const int B  = in_sizes[0] / TUN;           // 16384
    int nb = (B + ROWS - 1) / ROWS;             // 293
    if (nb > 512) nb = 512;

    const int smem_bytes = W_TOTAL * 4;         // ~99.3 KB
    cudaFuncSetAttribute(loss_kernel,
                         cudaFuncAttributeMaxDynamicSharedMemorySize, smem_bytes);
    loss_kernel<<<nb, THR, smem_bytes>>>(pred, dem, clu, caps, t2l, out,
                                         B, nb, 1.0f / (float)B);
}

// round 12
// speedup vs baseline: 1.0504x; 1.0504x over previous
#include <cuda_runtime.h>

#define EPSF 1e-8f
#define LNK   16
#define DST   255
#define TUN   1020
#define NCH   8
#define PAIRS 28          // row pairs per block
#define ROWS  56
#define SSTR  58          // words per group slot (28 pairs*2 + 2 pad)
#define PLW   (32*SSTR)   // 1856 words per plane
#define BUFDW (4*PLW)     // 7424 data words per buffer
#define BUFW  (BUFDW+64)  // + 64-word zero region per buffer
#define BUFB  (BUFW*4)    // 29952 bytes per buffer
#define ZBYTE (BUFDW*4)   // 29696: zero region byte offset (same in all buffers)
#define SCHW  144
#define THR   512

// dynamic smem layout (words)
#define W_SCHED (3*BUFW)
#define W_OFF   (W_SCHED + (NCH*SCHW)/2)
#define W_CUR   (W_OFF + NCH*17)
#define W_NL    (W_CUR + NCH*17)
#define W_INV   (W_NL + ROWS*17)
#define W_LOSS  (W_INV + 16)
#define W_FIN   (W_LOSS + 16)
#define W_LAST  (W_FIN + THR)
#define W_TOTAL (W_LAST + 1)

__device__ float    g_partials[512];
__device__ unsigned g_count;   // zero-init; last block resets (deterministic)

__device__ __forceinline__ unsigned long long lds64(unsigned a) {
    unsigned long long v;
    asm volatile("ld.shared.b64 %0, [%1];" : "=l"(v) : "r"(a));
    return v;
}
__device__ __forceinline__ unsigned long long addx2(unsigned long long a,
                                                    unsigned long long b) {
    unsigned long long r;
    asm("add.rn.f32x2 %0, %1, %2;" : "=l"(r) : "l"(a), "l"(b));
    return r;
}
// named barriers: each phase sees 512 arrives + 512 syncs -> count 1024
#define BAR_ARRIVE(id) asm volatile("bar.arrive %0, 1024;" :: "r"(id) : "memory")
#define BAR_SYNC(id)   asm volatile("bar.sync %0, 1024;"   :: "r"(id) : "memory")

__global__ __launch_bounds__(THR, 2) void loss_kernel(
    const float* __restrict__ pred,   // [B,1020]
    const float* __restrict__ dem,    // [B,255]
    const float* __restrict__ clu,    // [B,16]
    const float* __restrict__ caps,   // [16]
    const int*   __restrict__ t2l,    // [1020]
    float* __restrict__ out,
    int B, int nb, float invB)
{
    extern __shared__ float sm[];
    float*          s_pl    = sm;                          // 3 buffers
    unsigned short* s_sched = (unsigned short*)(sm + W_SCHED);
    int*            s_off   = (int*)(sm + W_OFF);          // [8][17]
    int*            s_cur   = (int*)(sm + W_CUR);
    float*          s_nl    = sm + W_NL;                   // [56][17]
    float*          s_inv   = sm + W_INV;
    float*          s_loss  = sm + W_LOSS;
    float*          s_fin   = sm + W_FIN;
    int*            s_last  = (int*)(sm + W_LAST);

    const int tid  = threadIdx.x;
    const int warp = tid >> 5;          // 0..15
    const int lane = tid & 31;
    const int base = blockIdx.x * ROWS;
    const unsigned pl32 = (unsigned)__cvta_generic_to_shared(s_pl);

    float4 ra[2], rb[2];
    float  da[2], db[2];
    unsigned long long acc0 = 0ull, acc1 = 0ull;

    #define LOADU(ch, u)                                                          \
    {                                                                             \
        const int gg = (ch) * 32 + lane;                                          \
        const int pr = warp + 16 * (u);                                           \
        const int r0 = base + pr, r1 = r0 + PAIRS;                                \
        const bool ok = (pr < PAIRS) && (gg < DST);                               \
        const bool o0 = ok && (r0 < B), o1 = ok && (r1 < B);                      \
        ra[u] = o0 ? ((const float4*)pred)[(size_t)r0 * DST + gg]                 \
                   : make_float4(0,0,0,0);                                        \
        rb[u] = o1 ? ((const float4*)pred)[(size_t)r1 * DST + gg]                 \
                   : make_float4(0,0,0,0);                                        \
        da[u] = o0 ? dem[(size_t)r0 * DST + gg] : 0.0f;                           \
        db[u] = o1 ? dem[(size_t)r1 * DST + gg] : 0.0f;                           \
    }

    #define STSU(buf, u)                                                          \
    {                                                                             \
        float* bp = s_pl + (buf) * BUFW;                                          \
        const int pr = warp + 16 * (u);                                           \
        if (pr < PAIRS) {                                                         \
            const int wb = lane * SSTR + pr * 2;                                  \
            ((float2*)bp)[(0 * PLW + wb) >> 1] = make_float2(ra[u].x * da[u], rb[u].x * db[u]); \
            ((float2*)bp)[(1 * PLW + wb) >> 1] = make_float2(ra[u].y * da[u], rb[u].y * db[u]); \
            ((float2*)bp)[(2 * PLW + wb) >> 1] = make_float2(ra[u].z * da[u], rb[u].z * db[u]); \
            ((float2*)bp)[(3 * PLW + wb) >> 1] = make_float2(ra[u].w * da[u], rb[u].w * db[u]); \
        }                                                                         \
    }

    #define GATHER(ch)                                                            \
    {                                                                             \
        const unsigned lbase = pl32 + (unsigned)(((ch) % 3) * BUFB)               \
                             + (unsigned)(lane << 3);                             \
        const unsigned short* sc = s_sched + (ch) * SCHW;                         \
        int k = s_off[(ch) * 17 + warp];                                          \
        const int hi = s_off[(ch) * 17 + warp + 1];                               \
        _Pragma("unroll 2")                                                       \
        for (; k < hi; k += 2) {                                                  \
            const unsigned o0 = sc[k];                                            \
            const unsigned o1 = sc[k + 1];                                        \
            acc0 = addx2(acc0, lds64(lbase + o0));                                \
            acc1 = addx2(acc1, lds64(lbase + o1));                                \
        }                                                                         \
    }

    // one pipeline step with literal chunk index c (all guards constant-fold)
    // barrier ids: full[b]=1+b, freed[b]=4+b  (id 0 reserved for __syncthreads)
    #define ITER(c)                                                               \
    {                                                                             \
        if ((c) + 1 < NCH) {                                                      \
            if ((c) + 1 >= 3) BAR_SYNC(4 + (((c) + 1) % 3));   /* buf freed */    \
            STSU(((c) + 1) % 3, 0);                                               \
            STSU(((c) + 1) % 3, 1);                                               \
            BAR_ARRIVE(1 + (((c) + 1) % 3));                   /* buf full  */    \
            if ((c) + 2 < NCH) { LOADU((c) + 2, 0); LOADU((c) + 2, 1); }          \
        }                                                                         \
        if ((c) >= 1) BAR_SYNC(1 + ((c) % 3));                 /* wait full */    \
        GATHER(c);                                                                \
        if ((c) + 3 < NCH) BAR_ARRIVE(4 + ((c) % 3));          /* mark freed */   \
    }

    // ------------- prologue --------------------------------------------------
    LOADU(0, 0); LOADU(0, 1);

    // schedule build: warp c (<8) sorts chunk c by bin
    if (warp < 8) {
        const int c = warp;
        int* cur = s_cur + c * 17;
        int* off = s_off + c * 17;
        if (lane < 17) cur[lane] = 0;
        int bins[4];
        #pragma unroll
        for (int q = 0; q < 4; ++q) {
            const int t = c * 128 + q * 32 + lane;
            bins[q] = (t < TUN) ? t2l[t] : 16;
        }
        __syncwarp();
        #pragma unroll
        for (int q = 0; q < 4; ++q) {
            const unsigned peers = __match_any_sync(0xffffffffu, bins[q]);
            const int rank = __popc(peers & ((1u << lane) - 1u));
            if (rank == 0) cur[bins[q]] += __popc(peers);
            __syncwarp();
        }
        if (lane < 17) {                           // padded (even) exclusive scan
            int o = 0;
            for (int i = 0; i < lane; ++i) o += (cur[i] + 1) & ~1;
            off[lane] = o;
        }
        __syncwarp();
        for (int i = lane; i < SCHW; i += 32)
            s_sched[c * SCHW + i] = (unsigned short)ZBYTE;   // dummy -> zeros
        if (lane < 17) cur[lane] = off[lane];
        __syncwarp();
        #pragma unroll
        for (int q = 0; q < 4; ++q) {
            const unsigned peers = __match_any_sync(0xffffffffu, bins[q]);
            const int rank = __popc(peers & ((1u << lane) - 1u));
            const int bse  = cur[bins[q]];
            __syncwarp();
            if (rank == 0) cur[bins[q]] = bse + __popc(peers);
            __syncwarp();
            if (bins[q] < 16) {
                const int tl = q * 32 + lane;
                const unsigned o = (unsigned)(tl & 3) * (PLW * 4)
                                 + (unsigned)(tl >> 2) * (SSTR * 4);
                s_sched[c * SCHW + bse + rank] = (unsigned short)o;
            }
        }
    }
    // zero regions of all THREE buffers
    if (tid >= 256 && tid < 448) {
        const int i = tid - 256;
        s_pl[(i >> 6) * BUFW + BUFDW + (i & 63)] = 0.0f;
    }
    if (tid < LNK) s_inv[tid] = 1.0f / (caps[tid] + EPSF);

    STSU(0, 0); STSU(0, 1);        // chunk 0 -> buffer 0
    LOADU(1, 0); LOADU(1, 1);
    __syncthreads();               // schedule + zeros + STS(0) all visible

    // ------------- fully unrolled pipeline -----------------------------------
    ITER(0); ITER(1); ITER(2); ITER(3);
    ITER(4); ITER(5); ITER(6); ITER(7);

    __syncthreads();               // all warps done before stats reuse smem

    // ------------- stats -----------------------------------------------------
    {
        const unsigned long long t = addx2(acc0, acc1);
        const float lo = __uint_as_float((unsigned)(t & 0xffffffffull));
        const float hi = __uint_as_float((unsigned)(t >> 32));
        if (lane < PAIRS) {
            s_nl[lane * 17 + warp] = lo;               // row = lane
            s_nl[(lane + PAIRS) * 17 + warp] = hi;     // row = lane + 28
        }
    }
    __syncthreads();

    float lsum = 0.0f;
    #pragma unroll
    for (int p = 0; p < 2; ++p) {
        const int rid = p * 32 + (warp << 1) + (lane >> 4);
        const int j = lane & 15;
        const int brow = base + rid;
        const bool rok = (rid < ROWS) && (brow < B);
        const float u   = rok ? s_nl[rid * 17 + j] * s_inv[j] : 0.0f;
        const float cur = rok ? clu[(size_t)brow * LNK + j] : 0.0f;

        float smn = u;
        #pragma unroll
        for (int off = 1; off < 16; off <<= 1)
            smn += __shfl_xor_sync(0xffffffffu, smn, off);
        const float mean = smn * (1.0f / 16.0f);

        const float dv = u - mean;
        float q2  = dv * dv;
        float dot = u * cur;
        float mx  = u;
        #pragma unroll
        for (int off = 1; off < 16; off <<= 1) {
            q2  += __shfl_xor_sync(0xffffffffu, q2, off);
            dot += __shfl_xor_sync(0xffffffffu, dot, off);
            mx   = fmaxf(mx, __shfl_xor_sync(0xffffffffu, mx, off));
        }
        if (j == 0 && rok)
            lsum += 0.3f * (q2 * (1.0f / 15.0f)) + 0.5f * dot + 0.2f * mx;
    }
    lsum += __shfl_xor_sync(0xffffffffu, lsum, 16);
    if (lane == 0) s_loss[warp] = lsum;
    __syncthreads();

    // ------------- deterministic single-launch reduction ---------------------
    if (tid == 0) {
        float t = 0.0f;
        #pragma unroll
        for (int w = 0; w < 16; ++w) t += s_loss[w];
        g_partials[blockIdx.x] = t;
        __threadfence();
        const unsigned old = atomicAdd(&g_count, 1u);
        *s_last = (old == (unsigned)(nb - 1));
    }
    __syncthreads();

    if (*s_last) {
        float v = 0.0f;
        for (int i = tid; i < nb; i += THR) v += __ldcg(&g_partials[i]);
        s_fin[tid] = v;
        __syncthreads();
        #pragma unroll
        for (int st = 256; st > 0; st >>= 1) {
            if (tid < st) s_fin[tid] += s_fin[tid + st];
            __syncthreads();
        }
        if (tid == 0) {
            out[0] = s_fin[0] * invB;
            g_count = 0;
        }
    }
}

extern "C" void kernel_launch(void* const* d_in, const int* in_sizes, int n_in,
                              void* d_out, int out_size)
{
    const float* pred = (const float*)d_in[0];
    const float* dem  = (const float*)d_in[1];
    const float* clu  = (const float*)d_in[2];
    const float* caps = (const float*)d_in[3];
    const int*   t2l  = (const int*)d_in[4];
    float* out = (float*)d_out;

    const int B  = in_sizes[0] / TUN;           // 16384
    int nb = (B + ROWS - 1) / ROWS;             // 293
    if (nb > 512) nb = 512;

    const int smem_bytes = W_TOTAL * 4;         // ~99.3 KB
    cudaFuncSetAttribute(loss_kernel,
                         cudaFuncAttributeMaxDynamicSharedMemorySize, smem_bytes);
    loss_kernel<<<nb, THR, smem_bytes>>>(pred, dem, clu, caps, t2l, out,
                                         B, nb, 1.0f / (float)B);
}